// round 1
// baseline (speedup 1.0000x reference)
#include <cuda_runtime.h>
#include <cuda_bf16.h>
#include <cstdint>
#include <cmath>

#define W 640
#define H 480
#define NPIX (W*H)
#define K 512
#define D 256
#define KP1 513
#define MAXC 32768

// ---------------- device scratch (no allocations allowed) ----------------
__device__ float g_scores[2][NPIX];
__device__ float g_smooth[2][NPIX];
__device__ float g_rowmax[2][NPIX];
__device__ unsigned long long g_cand[2][MAXC];
__device__ int g_ncand[2];
__device__ unsigned long long g_sel[2][K];
__device__ float g_desc[2][K*D];
__device__ float g_a2[2][K];
__device__ float g_Z[KP1*KP1];
__device__ float g_ZT[KP1*KP1];
__device__ float g_u[KP1];
__device__ float g_v[KP1];

struct Offs { signed char o[1024]; };

// ---------------- helpers ----------------
__device__ __forceinline__ float warpMax(float v){
    #pragma unroll
    for(int o=16;o;o>>=1) v = fmaxf(v, __shfl_xor_sync(0xffffffffu, v, o));
    return v;
}
__device__ __forceinline__ float warpSum(float v){
    #pragma unroll
    for(int o=16;o;o>>=1) v += __shfl_xor_sync(0xffffffffu, v, o);
    return v;
}

// ---------------- reset ----------------
__global__ void reset_kernel(){
    int t = blockIdx.x*256 + threadIdx.x;
    if (t < 2) g_ncand[t] = 0;
    if (t < 2*K) g_sel[t>>9][t&(K-1)] = 0ULL;
    if (t < KP1) { g_u[t] = 0.f; g_v[t] = 0.f; }
}

// ---------------- fused detector: scores + smooth ----------------
#define TX 32
#define TY 8
__global__ void detect_kernel(const float* __restrict__ img1, const float* __restrict__ img2){
    int z = blockIdx.z;
    const float* img = z ? img2 : img1;
    __shared__ float si[TY+4][TX+4];
    __shared__ float sxx[TY+2][TX+3];
    __shared__ float syy[TY+2][TX+3];
    __shared__ float sxy[TY+2][TX+3];
    int tid = threadIdx.y*TX + threadIdx.x;
    int gx0 = blockIdx.x*TX - 2, gy0 = blockIdx.y*TY - 2;
    for (int i = tid; i < (TY+4)*(TX+4); i += TX*TY){
        int r = i/(TX+4), c = i%(TX+4);
        int gy = gy0+r, gx = gx0+c;
        si[r][c] = (gy>=0 && gy<H && gx>=0 && gx<W) ? img[gy*W+gx] : 0.f;
    }
    __syncthreads();
    for (int i = tid; i < (TY+2)*(TX+2); i += TX*TY){
        int r = i/(TX+2), c = i%(TX+2);
        int gy = gy0+r+1, gx = gx0+c+1;
        float ix = 0.f, iy = 0.f;
        if (gy>=0 && gy<H && gx>=0 && gx<W){
            float a=si[r][c],   b=si[r][c+1],   cc=si[r][c+2];
            float d=si[r+1][c],                 f=si[r+1][c+2];
            float g=si[r+2][c], h=si[r+2][c+1], k=si[r+2][c+2];
            ix = (cc-a) + 2.f*(f-d) + (k-g);
            iy = (g-a)  + 2.f*(h-b) + (k-cc);
        }
        sxx[r][c] = ix*ix; syy[r][c] = iy*iy; sxy[r][c] = ix*iy;
    }
    __syncthreads();
    int lx = threadIdx.x, ly = threadIdx.y;
    float Sxx=0.f, Syy=0.f, Sxy=0.f;
    #pragma unroll
    for (int dy=0; dy<3; dy++)
        #pragma unroll
        for (int dx=0; dx<3; dx++){
            Sxx += sxx[ly+dy][lx+dx];
            Syy += syy[ly+dy][lx+dx];
            Sxy += sxy[ly+dy][lx+dx];
        }
    const float inv9 = 1.f/9.f;
    Sxx *= inv9; Syy *= inv9; Sxy *= inv9;
    float half = 0.5f*(Sxx+Syy);
    float diff = 0.5f*(Sxx-Syy);
    float score = half - sqrtf(diff*diff + Sxy*Sxy + 1e-12f);
    float sm = 0.f;
    #pragma unroll
    for (int dy=0; dy<5; dy++)
        #pragma unroll
        for (int dx=0; dx<5; dx++) sm += si[ly+dy][lx+dx];
    sm *= (1.f/25.f);
    int oy = blockIdx.y*TY+ly, ox = blockIdx.x*TX+lx;
    g_scores[z][oy*W+ox] = score;
    g_smooth[z][oy*W+ox] = sm;
}

// ---------------- NMS: separable 7x7 max ----------------
__global__ void rowmax_kernel(){
    int z = blockIdx.z;
    int x = blockIdx.x*TX + threadIdx.x;
    int y = blockIdx.y*TY + threadIdx.y;
    const float* s = g_scores[z] + y*W;
    float m = -1e30f;
    #pragma unroll
    for (int dx=-3; dx<=3; dx++){
        int xx = x+dx;
        if (xx>=0 && xx<W) m = fmaxf(m, s[xx]);
    }
    g_rowmax[z][y*W+x] = m;
}

__global__ void colmax_cand_kernel(){
    int z = blockIdx.z;
    int x = blockIdx.x*TX + threadIdx.x;
    int y = blockIdx.y*TY + threadIdx.y;
    float m = -1e30f;
    #pragma unroll
    for (int dy=-3; dy<=3; dy++){
        int yy = y+dy;
        if (yy>=0 && yy<H) m = fmaxf(m, g_rowmax[z][yy*W+x]);
    }
    float sc = g_scores[z][y*W+x];
    if (sc >= m - 1e-7f && sc > 0.f){
        int pos = atomicAdd(&g_ncand[z], 1);
        if (pos < MAXC){
            unsigned idx = (unsigned)(y*W + x);
            unsigned long long key =
                ((unsigned long long)__float_as_uint(sc) << 32) | (0xFFFFFFFFu - idx);
            g_cand[z][pos] = key;
        }
    }
}

// ---------------- top-512 by rank counting (stable like lax.top_k) ----------------
__global__ void rank_select_kernel(){
    int z = blockIdx.y;
    int n = min(g_ncand[z], MAXC);
    if ((int)(blockIdx.x*256) >= n) return;
    int c = blockIdx.x*256 + threadIdx.x;
    unsigned long long my = (c < n) ? g_cand[z][c] : 0ULL;
    __shared__ unsigned long long sk[2048];
    int cnt = 0;
    for (int base = 0; base < n; base += 2048){
        int m = min(2048, n - base);
        __syncthreads();
        for (int i = threadIdx.x; i < m; i += 256) sk[i] = g_cand[z][base+i];
        __syncthreads();
        if (c < n)
            for (int i = 0; i < m; i++) cnt += (sk[i] > my);
    }
    if (c < n && cnt < K) g_sel[z][cnt] = my;
}

// ---------------- descriptors at keypoints + kp output ----------------
__global__ void desc_kernel(Offs offs, float* __restrict__ out, int write_kp){
    int z = blockIdx.y, k = blockIdx.x, d = threadIdx.x;
    unsigned long long key = g_sel[z][k];
    bool valid = (key != 0ULL);
    int y = 0, x = 0;
    float val = 0.f;
    if (valid){
        unsigned idx = 0xFFFFFFFFu - (unsigned)(key & 0xFFFFFFFFu);
        y = (int)(idx / W); x = (int)(idx % W);
        int o0 = offs.o[d*4+0], o1 = offs.o[d*4+1];
        int o2 = offs.o[d*4+2], o3 = offs.o[d*4+3];
        int y1 = min(max(y+o0,0),H-1), x1 = min(max(x+o1,0),W-1);
        int y2 = min(max(y+o2,0),H-1), x2 = min(max(x+o3,0),W-1);
        val = g_smooth[z][y1*W+x1] - g_smooth[z][y2*W+x2];
    }
    // block reduce sum of squares (256 threads = 8 warps)
    __shared__ float shm[9];
    float ws = warpSum(val*val);
    int lane = threadIdx.x & 31, warp = threadIdx.x >> 5;
    if (lane == 0) shm[warp] = ws;
    __syncthreads();
    if (threadIdx.x == 0){
        float s = 0.f;
        #pragma unroll
        for (int q=0;q<8;q++) s += shm[q];
        shm[8] = s;
    }
    __syncthreads();
    float ss = shm[8];
    float inv = 1.f/(sqrtf(ss) + 1e-8f);
    g_desc[z][k*D + d] = val*inv;
    if (d == 0){
        g_a2[z][k] = ss*inv*inv;
        if (write_kp){
            float* kp = out + z*(K*2) + k*2;
            kp[0] = valid ? (float)y : -1.f;
            kp[1] = valid ? (float)x : -1.f;
        }
    }
}

// ---------------- Z = sim matrix with dustbins, plus transpose ----------------
__global__ void zbuild_kernel(){
    int j0 = blockIdx.x*16, i0 = blockIdx.y*16;
    int tx = threadIdx.x, ty = threadIdx.y;
    __shared__ float A[16][17], B[16][17];
    float acc = 0.f;
    const float* d1 = g_desc[0];
    const float* d2 = g_desc[1];
    int i = i0+ty, j = j0+tx;
    for (int k0 = 0; k0 < D; k0 += 16){
        A[ty][tx] = (i0+ty < K) ? d1[(i0+ty)*D + k0+tx] : 0.f;
        B[ty][tx] = (j0+tx < K) ? d2[(j0+tx)*D + k0+ty] : 0.f;
        __syncthreads();
        #pragma unroll
        for (int kk=0; kk<16; kk++) acc += A[ty][kk]*B[kk][tx];
        __syncthreads();
    }
    if (i < KP1 && j < KP1){
        float vZ;
        if (i < K && j < K){
            float sq = fmaxf(g_a2[0][i] + g_a2[1][j] - 2.f*acc, 0.f);
            vZ = -sqrtf(sq + 1e-12f);
        } else {
            vZ = 1.0f;   // dustbin score / EPSILON(=1)
        }
        g_Z [i*KP1 + j] = vZ;
        g_ZT[j*KP1 + i] = vZ;
    }
}

// ---------------- Sinkhorn half-iterations ----------------
// norm = -log(2K) = -log(1024); log_mu[i<K]=norm, log_mu[K]=log(K)+norm=-log(2)
#define NORM_C  (-6.93147182f)
#define DUST_C  (-0.69314718f)

__device__ __forceinline__ void lse_row(const float* __restrict__ M,
                                        const float* __restrict__ add,
                                        float* __restrict__ dst, int i, float lm){
    int t = threadIdx.x;
    const float* r = M + i*KP1;
    float v0 = r[t]      + add[t];
    float v1 = r[t+256]  + add[t+256];
    float v2 = (t==0) ? (r[512] + add[512]) : -1e30f;
    float mx = fmaxf(fmaxf(v0,v1),v2);
    __shared__ float shm[9];
    float wm = warpMax(mx);
    int lane = t & 31, warp = t >> 5;
    if (lane==0) shm[warp] = wm;
    __syncthreads();
    if (t==0){
        float m = shm[0];
        #pragma unroll
        for (int q=1;q<8;q++) m = fmaxf(m, shm[q]);
        shm[8] = m;
    }
    __syncthreads();
    float m = shm[8];
    float s = __expf(v0-m) + __expf(v1-m) + __expf(v2-m);
    float wsum = warpSum(s);
    __syncthreads();
    if (lane==0) shm[warp] = wsum;
    __syncthreads();
    if (t==0){
        float tot = 0.f;
        #pragma unroll
        for (int q=0;q<8;q++) tot += shm[q];
        dst[i] = lm - (m + __logf(tot));
    }
}

__global__ void sink_u_kernel(){
    int i = blockIdx.x;
    lse_row(g_Z,  g_v, g_u, i, (i==K) ? DUST_C : NORM_C);
}
__global__ void sink_v_kernel(){
    int j = blockIdx.x;
    lse_row(g_ZT, g_u, g_v, j, (j==K) ? DUST_C : NORM_C);
}

// ---------------- final probs ----------------
__global__ void probs_kernel(float* __restrict__ out){
    int idx = blockIdx.x*256 + threadIdx.x;
    if (idx >= KP1*KP1) return;
    int i = idx / KP1, j = idx % KP1;
    out[idx] = __expf(g_Z[idx] + g_u[i] + g_v[j] + 6.93147182f);
}

// ---------------- host: MT19937 for BAD pattern (numpy RandomState(42)) ----------------
static void make_offsets(Offs& offs){
    uint32_t mt[624];
    mt[0] = 42u;
    for (int i = 1; i < 624; i++)
        mt[i] = 1812433253u * (mt[i-1] ^ (mt[i-1] >> 30)) + (uint32_t)i;
    int mti = 624;
    auto next = [&]() -> uint32_t {
        if (mti >= 624){
            for (int i = 0; i < 624; i++){
                uint32_t y = (mt[i] & 0x80000000u) | (mt[(i+1)%624] & 0x7fffffffu);
                mt[i] = mt[(i+397)%624] ^ (y >> 1) ^ ((y & 1u) ? 2567483615u : 0u);
            }
            mti = 0;
        }
        uint32_t y = mt[mti++];
        y ^= y >> 11;
        y ^= (y << 7)  & 2636928640u;
        y ^= (y << 15) & 4022730752u;
        y ^= y >> 18;
        return y;
    };
    for (int i = 0; i < 1024; i++){
        uint32_t a = next() >> 5, b = next() >> 6;
        double s = ((double)a * 67108864.0 + (double)b) / 9007199254740992.0;
        double val = -8.0 + 16.0 * s;           // uniform(-8, 8)
        offs.o[i] = (signed char)nearbyint(val); // np.round = ties-to-even
    }
}

extern "C" void kernel_launch(void* const* d_in, const int* in_sizes, int n_in,
                              void* d_out, int out_size){
    const float* img1 = (const float*)d_in[0];
    const float* img2 = (const float*)d_in[1];
    float* out = (float*)d_out;

    Offs offs;
    make_offsets(offs);

    int write_kp   = (out_size >= 2*K*2 + KP1*KP1) ? 1 : 0;
    int probs_off  = write_kp ? (2*K*2) : 0;

    reset_kernel<<<5, 256>>>();
    detect_kernel<<<dim3(W/TX, H/TY, 2), dim3(TX, TY)>>>(img1, img2);
    rowmax_kernel<<<dim3(W/TX, H/TY, 2), dim3(TX, TY)>>>();
    colmax_cand_kernel<<<dim3(W/TX, H/TY, 2), dim3(TX, TY)>>>();
    rank_select_kernel<<<dim3(MAXC/256, 2), 256>>>();
    desc_kernel<<<dim3(K, 2), 256>>>(offs, out, write_kp);
    zbuild_kernel<<<dim3(33, 33), dim3(16, 16)>>>();
    for (int it = 0; it < 20; it++){
        sink_u_kernel<<<KP1, 256>>>();
        sink_v_kernel<<<KP1, 256>>>();
    }
    probs_kernel<<<(KP1*KP1 + 255)/256, 256>>>(out + probs_off);
}

// round 2
// speedup vs baseline: 1.0231x; 1.0231x over previous
#include <cuda_runtime.h>
#include <cuda_bf16.h>
#include <cstdint>
#include <cmath>

#define W 640
#define H 480
#define NPIX (W*H)
#define K 512
#define D 256
#define KP1 513
#define MAXC 32768

// ---------------- device scratch (no allocations allowed) ----------------
__device__ float g_smooth[2][NPIX];
__device__ unsigned long long g_cand[2][MAXC];
__device__ int g_ncand[2];
__device__ int g_cnt[2][MAXC];
__device__ unsigned long long g_sel[2][K];
__device__ float g_desc[2][K*D];
__device__ float g_a2[2][K];
__device__ float g_E[KP1*KP1];
__device__ float g_ET[KP1*KP1];
__device__ float g_eu[KP1];
__device__ float g_ev[KP1];
__device__ unsigned g_bar_count;
__device__ unsigned g_bar_gen;

struct Offs { signed char o[1024]; };

// ---------------- helpers ----------------
__device__ __forceinline__ float warpSum(float v){
    #pragma unroll
    for(int o=16;o;o>>=1) v += __shfl_xor_sync(0xffffffffu, v, o);
    return v;
}

// ---------------- reset ----------------
__global__ void reset_kernel(){
    int t = blockIdx.x*256 + threadIdx.x;          // 65536 threads
    g_cnt[t>>15][t & (MAXC-1)] = 0;
    if (t < 2*K) g_sel[t>>9][t & (K-1)] = 0ULL;
    if (t < KP1) g_ev[t] = 1.0f;
    if (t < 2) g_ncand[t] = 0;
    if (t == 0){ g_bar_count = 0; g_bar_gen = 0; }
}

// ---------------- fused detector + smooth + NMS + candidates ----------------
#define TX 32
#define TY 8
// img halo 5 (2 grad+box, 3 NMS)
__global__ void detect_nms_kernel(const float* __restrict__ img1, const float* __restrict__ img2){
    int z = blockIdx.z;
    const float* img = z ? img2 : img1;
    __shared__ float si[18][44];     // (TY+10) x (TX+10)
    __shared__ float sxx[16][41];    // (TY+8) x (TX+8)
    __shared__ float syy[16][41];
    __shared__ float sxy[16][41];
    __shared__ float sc[14][39];     // (TY+6) x (TX+6)
    __shared__ float rm[14][33];     // rowmax

    int tid = threadIdx.y*TX + threadIdx.x;
    int gx0 = blockIdx.x*TX, gy0 = blockIdx.y*TY;

    // stage A: load image tile with halo 5, zero pad
    for (int i = tid; i < 18*42; i += 256){
        int r = i/42, c = i - r*42;
        int gy = gy0 - 5 + r, gx = gx0 - 5 + c;
        si[r][c] = (gy>=0 && gy<H && gx>=0 && gx<W) ? img[gy*W+gx] : 0.f;
    }
    __syncthreads();

    // stage B: gradient products (region halo 4); zero when pixel outside image
    for (int i = tid; i < 16*40; i += 256){
        int r = i/40, c = i - r*40;
        int gy = gy0 - 4 + r, gx = gx0 - 4 + c;
        float ix = 0.f, iy = 0.f;
        if (gy>=0 && gy<H && gx>=0 && gx<W){
            float a=si[r][c],   b=si[r][c+1],   cc=si[r][c+2];
            float d=si[r+1][c],                 f=si[r+1][c+2];
            float g=si[r+2][c], h=si[r+2][c+1], k=si[r+2][c+2];
            ix = (cc-a) + 2.f*(f-d) + (k-g);
            iy = (g-a)  + 2.f*(h-b) + (k-cc);
        }
        sxx[r][c] = ix*ix; syy[r][c] = iy*iy; sxy[r][c] = ix*iy;
    }
    __syncthreads();

    // stage C: scores (region halo 3); -inf outside image
    for (int i = tid; i < 14*38; i += 256){
        int rs = i/38, cs = i - rs*38;
        int gy = gy0 - 3 + rs, gx = gx0 - 3 + cs;
        float v = -1e30f;
        if (gy>=0 && gy<H && gx>=0 && gx<W){
            float Sxx=0.f, Syy=0.f, Sxy=0.f;
            #pragma unroll
            for (int dy=0; dy<3; dy++)
                #pragma unroll
                for (int dx=0; dx<3; dx++){
                    Sxx += sxx[rs+dy][cs+dx];
                    Syy += syy[rs+dy][cs+dx];
                    Sxy += sxy[rs+dy][cs+dx];
                }
            const float inv9 = 1.f/9.f;
            Sxx *= inv9; Syy *= inv9; Sxy *= inv9;
            float half = 0.5f*(Sxx+Syy);
            float diff = 0.5f*(Sxx-Syy);
            v = half - sqrtf(diff*diff + Sxy*Sxy + 1e-12f);
        }
        sc[rs][cs] = v;
    }
    __syncthreads();

    // stage D: separable NMS rowmax (7 wide)
    for (int i = tid; i < 14*32; i += 256){
        int r = i/32, c = i - r*32;
        float m = sc[r][c];
        #pragma unroll
        for (int dx=1; dx<7; dx++) m = fmaxf(m, sc[r][c+dx]);
        rm[r][c] = m;
    }
    __syncthreads();

    // stage E: colmax + smooth + candidate emit (one output pixel / thread)
    int lx = threadIdx.x, ly = threadIdx.y;
    float cm = rm[ly][lx];
    #pragma unroll
    for (int dy=1; dy<7; dy++) cm = fmaxf(cm, rm[ly+dy][lx]);
    float self = sc[ly+3][lx+3];

    float sm = 0.f;
    #pragma unroll
    for (int dy=0; dy<5; dy++)
        #pragma unroll
        for (int dx=0; dx<5; dx++) sm += si[ly+3+dy][lx+3+dx];
    sm *= (1.f/25.f);

    int oy = gy0+ly, ox = gx0+lx;
    g_smooth[z][oy*W+ox] = sm;

    if (self > 0.f && self >= cm - 1e-7f){
        int pos = atomicAdd(&g_ncand[z], 1);
        if (pos < MAXC){
            unsigned idx = (unsigned)(oy*W + ox);
            g_cand[z][pos] = ((unsigned long long)__float_as_uint(self) << 32)
                             | (0xFFFFFFFFu - idx);
        }
    }
}

// ---------------- top-512: tile-pair rank counting ----------------
__global__ void count_kernel(){
    __shared__ unsigned long long sk[256];
    int n0 = min(g_ncand[0], MAXC);
    int n1 = min(g_ncand[1], MAXC);
    int c0 = (n0 + 255) >> 8;
    int c1 = (n1 + 255) >> 8;
    int t0 = c0*c0;
    int total = t0 + c1*c1;
    for (int p = blockIdx.x; p < total; p += gridDim.x){
        int z, pp, cz, n;
        if (p < t0){ z = 0; pp = p; cz = c0; n = n0; }
        else       { z = 1; pp = p - t0; cz = c1; n = n1; }
        int ci = pp / cz, ij = pp - ci*cz;
        int c  = ci*256 + threadIdx.x;
        int ib = ij*256;
        unsigned long long my = (c < n) ? g_cand[z][c] : 0ULL;
        int m = min(256, n - ib);
        __syncthreads();
        if (threadIdx.x < m) sk[threadIdx.x] = g_cand[z][ib + threadIdx.x];
        __syncthreads();
        if (c < n){
            int cnt = 0;
            for (int i = 0; i < m; i++) cnt += (sk[i] > my);
            if (cnt) atomicAdd(&g_cnt[z][c], cnt);
        }
    }
}

__global__ void scatter_kernel(){
    int z = blockIdx.y;
    int n = min(g_ncand[z], MAXC);
    int c = blockIdx.x*256 + threadIdx.x;
    if (c < n){
        int cnt = g_cnt[z][c];
        if (cnt < K) g_sel[z][cnt] = g_cand[z][c];
    }
}

// ---------------- descriptors at keypoints + kp output ----------------
__global__ void desc_kernel(Offs offs, float* __restrict__ out, int write_kp){
    int z = blockIdx.y, k = blockIdx.x, d = threadIdx.x;
    unsigned long long key = g_sel[z][k];
    bool valid = (key != 0ULL);
    int y = 0, x = 0;
    float val = 0.f;
    if (valid){
        unsigned idx = 0xFFFFFFFFu - (unsigned)(key & 0xFFFFFFFFu);
        y = (int)(idx / W); x = (int)(idx % W);
        int o0 = offs.o[d*4+0], o1 = offs.o[d*4+1];
        int o2 = offs.o[d*4+2], o3 = offs.o[d*4+3];
        int y1 = min(max(y+o0,0),H-1), x1 = min(max(x+o1,0),W-1);
        int y2 = min(max(y+o2,0),H-1), x2 = min(max(x+o3,0),W-1);
        val = g_smooth[z][y1*W+x1] - g_smooth[z][y2*W+x2];
    }
    __shared__ float shm[9];
    float ws = warpSum(val*val);
    int lane = threadIdx.x & 31, warp = threadIdx.x >> 5;
    if (lane == 0) shm[warp] = ws;
    __syncthreads();
    if (threadIdx.x == 0){
        float s = 0.f;
        #pragma unroll
        for (int q=0;q<8;q++) s += shm[q];
        shm[8] = s;
    }
    __syncthreads();
    float ss = shm[8];
    float inv = 1.f/(sqrtf(ss) + 1e-8f);
    g_desc[z][k*D + d] = val*inv;
    if (d == 0){
        g_a2[z][k] = ss*inv*inv;
        if (write_kp){
            float* kp = out + z*(K*2) + k*2;
            kp[0] = valid ? (float)y : -1.f;
            kp[1] = valid ? (float)x : -1.f;
        }
    }
}

// ---------------- E = exp(sim/eps) with dustbins, plus transpose ----------------
// 32x32 output tile, 16x16 threads, 2x2 per thread
__global__ void ebuild_kernel(){
    __shared__ float As[32][33], Bs[32][33];
    int tx = threadIdx.x, ty = threadIdx.y;
    int tid = ty*16 + tx;
    int i0 = blockIdx.y*32, j0 = blockIdx.x*32;
    const float* d1 = g_desc[0];
    const float* d2 = g_desc[1];
    float c00=0.f,c01=0.f,c10=0.f,c11=0.f;
    for (int k0 = 0; k0 < D; k0 += 32){
        #pragma unroll
        for (int e = 0; e < 4; e++){
            int lin = tid + e*256;
            int m = lin >> 5, kk = lin & 31;
            As[m][kk] = (i0+m < K) ? d1[(i0+m)*D + k0+kk] : 0.f;
            Bs[kk][m] = (j0+m < K) ? d2[(j0+m)*D + k0+kk] : 0.f;
        }
        __syncthreads();
        #pragma unroll
        for (int kk=0; kk<32; kk++){
            float a0 = As[ty][kk],    a1 = As[ty+16][kk];
            float b0 = Bs[kk][tx],    b1 = Bs[kk][tx+16];
            c00 += a0*b0; c01 += a0*b1; c10 += a1*b0; c11 += a1*b1;
        }
        __syncthreads();
    }
    #pragma unroll
    for (int ei = 0; ei < 2; ei++){
        #pragma unroll
        for (int ej = 0; ej < 2; ej++){
            int i = i0 + ty + ei*16;
            int j = j0 + tx + ej*16;
            if (i < KP1 && j < KP1){
                float Eij;
                if (i < K && j < K){
                    float acc = ei ? (ej ? c11 : c10) : (ej ? c01 : c00);
                    float sq = fmaxf(g_a2[0][i] + g_a2[1][j] - 2.f*acc, 0.f);
                    Eij = __expf(-sqrtf(sq + 1e-12f));
                } else {
                    Eij = 2.718281828f;   // exp(dustbin 1.0 / eps 1.0)
                }
                g_E [i*KP1 + j] = Eij;
                g_ET[j*KP1 + i] = Eij;
            }
        }
    }
}

// ---------------- fused Sinkhorn (multiplicative) + probs ----------------
__device__ __forceinline__ void grid_barrier(unsigned target, unsigned &gen){
    __syncthreads();
    if (threadIdx.x == 0){
        __threadfence();
        unsigned t = atomicAdd(&g_bar_count, 1u);
        if (t == target - 1u){
            g_bar_count = 0u;
            __threadfence();
            atomicAdd(&g_bar_gen, 1u);
        } else {
            while (*(volatile unsigned*)&g_bar_gen == gen) { }
            __threadfence();
        }
    }
    gen++;
    __syncthreads();
}

#define SINK_BLOCKS 148

__global__ void __launch_bounds__(256, 1) sink_kernel(float* __restrict__ out){
    unsigned gen = 0;
    int warp = threadIdx.x >> 5, lane = threadIdx.x & 31;
    int r = blockIdx.x*8 + warp;
    bool active = (r < KP1);
    int rr = active ? r : 0;
    const float* __restrict__ Er  = g_E  + rr*KP1;
    const float* __restrict__ ETr = g_ET + rr*KP1;
    float mu = (r == K) ? 0.5f : (1.0f/1024.0f);

    #pragma unroll 1
    for (int it = 0; it < 20; it++){
        if (active){
            float s = 0.f;
            #pragma unroll 4
            for (int j = lane; j < KP1; j += 32) s += Er[j]*g_ev[j];
            s = warpSum(s);
            if (lane == 0) g_eu[r] = mu / s;
        }
        grid_barrier(SINK_BLOCKS, gen);
        if (active){
            float s = 0.f;
            #pragma unroll 4
            for (int i = lane; i < KP1; i += 32) s += ETr[i]*g_eu[i];
            s = warpSum(s);
            if (lane == 0) g_ev[r] = mu / s;
        }
        grid_barrier(SINK_BLOCKS, gen);
    }
    // probs = 1024 * E * eu_i * ev_j
    int gsz = gridDim.x * blockDim.x;
    for (int idx = blockIdx.x*blockDim.x + threadIdx.x; idx < KP1*KP1; idx += gsz){
        int i = idx / KP1;
        int j = idx - i*KP1;
        out[idx] = g_E[idx] * g_eu[i] * g_ev[j] * 1024.0f;
    }
}

// ---------------- host: MT19937 for BAD pattern (numpy RandomState(42)) ----------------
static void make_offsets(Offs& offs){
    uint32_t mt[624];
    mt[0] = 42u;
    for (int i = 1; i < 624; i++)
        mt[i] = 1812433253u * (mt[i-1] ^ (mt[i-1] >> 30)) + (uint32_t)i;
    int mti = 624;
    auto next = [&]() -> uint32_t {
        if (mti >= 624){
            for (int i = 0; i < 624; i++){
                uint32_t y = (mt[i] & 0x80000000u) | (mt[(i+1)%624] & 0x7fffffffu);
                mt[i] = mt[(i+397)%624] ^ (y >> 1) ^ ((y & 1u) ? 2567483615u : 0u);
            }
            mti = 0;
        }
        uint32_t y = mt[mti++];
        y ^= y >> 11;
        y ^= (y << 7)  & 2636928640u;
        y ^= (y << 15) & 4022730752u;
        y ^= y >> 18;
        return y;
    };
    for (int i = 0; i < 1024; i++){
        uint32_t a = next() >> 5, b = next() >> 6;
        double s = ((double)a * 67108864.0 + (double)b) / 9007199254740992.0;
        double val = -8.0 + 16.0 * s;            // uniform(-8, 8)
        offs.o[i] = (signed char)nearbyint(val); // np.round = ties-to-even
    }
}

extern "C" void kernel_launch(void* const* d_in, const int* in_sizes, int n_in,
                              void* d_out, int out_size){
    const float* img1 = (const float*)d_in[0];
    const float* img2 = (const float*)d_in[1];
    float* out = (float*)d_out;

    Offs offs;
    make_offsets(offs);

    int write_kp  = (out_size >= 2*K*2 + KP1*KP1) ? 1 : 0;
    int probs_off = write_kp ? (2*K*2) : 0;

    reset_kernel<<<256, 256>>>();
    detect_nms_kernel<<<dim3(W/TX, H/TY, 2), dim3(TX, TY)>>>(img1, img2);
    count_kernel<<<296, 256>>>();
    scatter_kernel<<<dim3(MAXC/256, 2), 256>>>();
    desc_kernel<<<dim3(K, 2), 256>>>(offs, out, write_kp);
    ebuild_kernel<<<dim3(17, 17), dim3(16, 16)>>>();
    sink_kernel<<<SINK_BLOCKS, 256>>>(out + probs_off);
}